// round 1
// baseline (speedup 1.0000x reference)
#include <cuda_runtime.h>
#include <math.h>

#define N_SAMP 4096
#define V 256
#define VM1 255
#define NH 64
#define NCOLS (V * NH)   // 16384 GEMM output columns (c*64 + h)

// Precomputed B matrix for the big GEMM: g_W[j][gc] = adj[j,c] * w_in[c, k(j), h]
// (zero where j == c). Row-major K=256 x NCOLS=16384. 16.8 MB -> lives in L2.
__device__ float g_W[V * NCOLS];
// Fused gate: g_gate[c*64+h] = neurons[h,c] * w_out[c,h]
__device__ float g_gate[NCOLS];

// ---------------------------------------------------------------------------
// Prep: fold adj into w_in, fold neurons into w_out.
// ---------------------------------------------------------------------------
__global__ void prep_kernel(const float* __restrict__ adj,
                            const float* __restrict__ w_in,
                            const float* __restrict__ neurons,
                            const float* __restrict__ w_out) {
    int idx = blockIdx.x * blockDim.x + threadIdx.x;
    if (idx < V * NCOLS) {
        int j  = idx / NCOLS;
        int gc = idx - j * NCOLS;
        int c  = gc >> 6;
        int h  = gc & 63;
        float w = 0.0f;
        if (j != c) {
            int k = j - (j > c ? 1 : 0);
            w = adj[j * V + c] * w_in[(c * VM1 + k) * NH + h];
        }
        g_W[idx] = w;
    }
    if (idx < NCOLS) {
        int c = idx >> 6, h = idx & 63;
        g_gate[idx] = neurons[h * V + c] * w_out[idx];
    }
}

// ---------------------------------------------------------------------------
// Copy adj verbatim into the first V*V floats of the output (tuple element 0).
// ---------------------------------------------------------------------------
__global__ void copy_adj_kernel(const float* __restrict__ adj, float* __restrict__ out) {
    int i = blockIdx.x * blockDim.x + threadIdx.x;
    if (i < V * V) out[i] = adj[i];
}

// ---------------------------------------------------------------------------
// Fused GEMM + tanh + gated reduction.
//   pre[n, gc] = sum_j data[n,j] * g_W[j, gc]          (M=4096, N=16384, K=256)
//   out[n, c]  = sum_{h} tanh(pre + b_in[gc]) * g_gate[gc] + b_out[c]
// Tile: 128x128x16, 256 threads, 8x8 per thread. Each 128-col tile = 2 channels.
// ---------------------------------------------------------------------------
#define BM 128
#define BN 128
#define BK 16
#define TM 8
#define TN 8

__global__ __launch_bounds__(256) void fused_gemm_kernel(
    const float* __restrict__ data,
    const float* __restrict__ b_in,
    const float* __restrict__ b_out,
    float* __restrict__ out)
{
    __shared__ float As[BK][BM];   // transposed A tile
    __shared__ float Bs[BK][BN];

    const int tid = threadIdx.x;
    const int tx = tid & 15;       // 0..15 -> column group
    const int ty = tid >> 4;       // 0..15 -> row group
    const int row_base = blockIdx.y * BM;
    const int col_base = blockIdx.x * BN;

    float acc[TM][TN];
    #pragma unroll
    for (int i = 0; i < TM; i++)
        #pragma unroll
        for (int j = 0; j < TN; j++)
            acc[i][j] = 0.0f;

    // A-load mapping: 128 rows x 4 float4 per row = 512 float4, 2 per thread.
    const int a_r0  = (tid * 2) >> 3;        // row for this thread's pair... (recomputed in loop)
    (void)a_r0;

    for (int k0 = 0; k0 < V; k0 += BK) {
        // --- load A tile (data is row-major N_SAMP x V) ---
        #pragma unroll
        for (int t = 0; t < 2; t++) {
            int f  = tid + t * 256;          // 0..511 float4 slots
            int r  = f >> 2;                 // 0..127
            int kq = f & 3;                  // which float4 within BK=16
            float4 v = *(const float4*)&data[(row_base + r) * V + k0 + kq * 4];
            As[kq * 4 + 0][r] = v.x;
            As[kq * 4 + 1][r] = v.y;
            As[kq * 4 + 2][r] = v.z;
            As[kq * 4 + 3][r] = v.w;
        }
        // --- load B tile (g_W is row-major V x NCOLS) ---
        #pragma unroll
        for (int t = 0; t < 2; t++) {
            int f  = tid + t * 256;          // 0..511 float4 slots (16 rows x 32 f4)
            int kk = f >> 5;                 // 0..15
            int nq = f & 31;                 // 0..31
            float4 v = *(const float4*)&g_W[(k0 + kk) * NCOLS + col_base + nq * 4];
            *(float4*)&Bs[kk][nq * 4] = v;
        }
        __syncthreads();

        #pragma unroll
        for (int k = 0; k < BK; k++) {
            float a[TM], b[TN];
            #pragma unroll
            for (int i = 0; i < TM; i++) a[i] = As[k][ty * TM + i];
            #pragma unroll
            for (int j = 0; j < TN; j++) b[j] = Bs[k][tx * TN + j];
            #pragma unroll
            for (int i = 0; i < TM; i++)
                #pragma unroll
                for (int j = 0; j < TN; j++)
                    acc[i][j] = fmaf(a[i], b[j], acc[i][j]);
        }
        __syncthreads();
    }

    // --- fused epilogue: tanh, gate, reduce over h (64 cols per channel) ---
    // This thread's 8 columns all belong to one channel (tx*8..tx*8+7 within
    // a 64-wide h-block since 8 | 64). Channel: c = col_base/64 + (tx>=8).
    const int c = (col_base >> 6) + (tx >> 3);

    float partial[TM];
    #pragma unroll
    for (int i = 0; i < TM; i++) partial[i] = 0.0f;

    #pragma unroll
    for (int j = 0; j < TN; j++) {
        int gc = col_base + tx * TN + j;     // == c*64 + h
        float bi = b_in[gc];
        float gt = g_gate[gc];
        #pragma unroll
        for (int i = 0; i < TM; i++)
            partial[i] += tanhf(acc[i][j] + bi) * gt;
    }

    // Reduce across the 8 threads (tx%8 == 0..7) sharing this channel.
    // Lane layout: lane = (ty&1)*16 + tx -> each 8-lane group is aligned.
    #pragma unroll
    for (int off = 4; off >= 1; off >>= 1) {
        #pragma unroll
        for (int i = 0; i < TM; i++)
            partial[i] += __shfl_xor_sync(0xffffffffu, partial[i], off);
    }

    if ((tx & 7) == 0) {
        float bo = b_out[c];
        #pragma unroll
        for (int i = 0; i < TM; i++) {
            int n = row_base + ty * TM + i;
            out[n * V + c] = partial[i] + bo;
        }
    }
}

// ---------------------------------------------------------------------------
extern "C" void kernel_launch(void* const* d_in, const int* in_sizes, int n_in,
                              void* d_out, int out_size) {
    const float* data    = (const float*)d_in[0];
    const float* adj     = (const float*)d_in[1];
    const float* neurons = (const float*)d_in[2];
    const float* w_in    = (const float*)d_in[3];
    const float* b_in    = (const float*)d_in[4];
    const float* w_out   = (const float*)d_in[5];
    const float* b_out   = (const float*)d_in[6];
    // d_in[7] = perm: structure is known analytically; never read.

    float* outp = (float*)d_out;
    int adj_off = out_size - N_SAMP * V;   // expected V*V = 65536
    if (adj_off >= V * V) {
        copy_adj_kernel<<<(V * V + 255) / 256, 256>>>(adj, outp);
    }
    float* out_main = outp + (adj_off > 0 ? adj_off : 0);

    prep_kernel<<<(V * NCOLS + 255) / 256, 256>>>(adj, w_in, neurons, w_out);

    dim3 grid(NCOLS / BN, N_SAMP / BM);
    fused_gemm_kernel<<<grid, 256>>>(data, b_in, b_out, out_main);
}

// round 3
// speedup vs baseline: 8.0644x; 8.0644x over previous
#include <cuda_runtime.h>
#include <cuda_fp16.h>
#include <cstdint>

#define N_SAMP 4096
#define V 256
#define VM1 255
#define NH 64
#define NCOLS (V * NH)   // 16384

// fp16 operands for the warp-mma GEMM
__device__ __half g_Ah[N_SAMP * V];   // data as fp16 [4096][256]
__device__ __half g_Bh[NCOLS * V];    // B^T: [gc][j] = adj[j,c]*w_in[c,k(j),h]
__device__ float  g_gate[NCOLS];      // neurons[h,c]*w_out[c,h]

__device__ __forceinline__ uint32_t smem_u32(const void* p) {
    uint32_t a;
    asm("{ .reg .u64 t; cvta.to.shared.u64 t, %1; cvt.u32.u64 %0, t; }" : "=r"(a) : "l"(p));
    return a;
}
__device__ __forceinline__ float tanh_fast(float x) {
    float y; asm("tanh.approx.f32 %0, %1;" : "=f"(y) : "f"(x)); return y;
}
#define CP_ASYNC16(dst_u32, src_ptr) \
    asm volatile("cp.async.cg.shared.global [%0], [%1], 16;" :: "r"(dst_u32), "l"(src_ptr) : "memory")
#define CP_COMMIT() asm volatile("cp.async.commit_group;" ::: "memory")

// ---------------------------------------------------------------------------
// Prep A: fp16 convert data, copy adj to output head, build gate
// ---------------------------------------------------------------------------
__global__ void prep_a_kernel(const float* __restrict__ data,
                              const float* __restrict__ adj,
                              const float* __restrict__ neurons,
                              const float* __restrict__ w_out,
                              float* __restrict__ out_adj) {
    int idx = blockIdx.x * 256 + threadIdx.x;
    if (idx < N_SAMP * V) g_Ah[idx] = __float2half_rn(data[idx]);
    if (idx < V * V) out_adj[idx] = adj[idx];
    if (idx < NCOLS) {
        int c = idx >> 6, h = idx & 63;
        g_gate[idx] = neurons[h * V + c] * w_out[idx];
    }
}

// ---------------------------------------------------------------------------
// Prep B: fold adj into w_in and transpose to [gc][j] fp16 via SMEM tile.
// ---------------------------------------------------------------------------
__global__ __launch_bounds__(256) void prep_b_kernel(const float* __restrict__ adj,
                                                     const float* __restrict__ w_in) {
    __shared__ float s[64][65];
    __shared__ float adjv[64];
    const int c   = blockIdx.x;
    const int jb  = blockIdx.y;
    const int tid = threadIdx.x;
    const int h   = tid & 63;
    const int kk4 = tid >> 6;

    if (tid < 64) {
        int j = jb * 64 + tid;
        adjv[tid] = (j == c) ? 0.0f : adj[j * V + c];
    }
    #pragma unroll
    for (int jj0 = 0; jj0 < 64; jj0 += 4) {
        int jj = jj0 + kk4;
        int j  = jb * 64 + jj;
        float w = 0.0f;
        if (j != c) {
            int k = j - (j > c ? 1 : 0);
            w = w_in[(c * VM1 + k) * NH + h];
        }
        s[jj][h] = w;
    }
    __syncthreads();
    #pragma unroll
    for (int h0 = 0; h0 < 64; h0 += 4) {
        int hh = h0 + (tid >> 6);
        int jj = tid & 63;
        float w = s[jj][hh] * adjv[jj];
        g_Bh[(c * 64 + hh) * V + jb * 64 + jj] = __float2half_rn(w);
    }
}

// ---------------------------------------------------------------------------
// Fused GEMM (mma.sync m16n8k16 fp16->fp32) + tanh/gate/h-reduce epilogue.
// CTA: 128x128 tile, BK=64, double-buffered cp.async. 8 warps as 4x2:
// warp tile 32 rows x 64 cols (one full channel).
// ---------------------------------------------------------------------------
#define BK 64
#define STAGE_BYTES 32768   // A 128x128B + B 128x128B

__global__ __launch_bounds__(256, 2)
void fused_mma_kernel(const float* __restrict__ b_in,
                      const float* __restrict__ b_out,
                      float* __restrict__ out) {
    extern __shared__ __align__(16) char smem[];
    const uint32_t sb = smem_u32(smem);

    const int tid  = threadIdx.x;
    const int wid  = tid >> 5;
    const int lane = tid & 31;
    const int wr   = wid & 3;        // warp row: rows wr*32
    const int wc   = wid >> 2;       // warp col: channel (0/1) within CTA

    const int m0  = blockIdx.y * 128;
    const int gc0 = blockIdx.x * 128;

    // per-thread load slots: id = tid + i*256 -> (r, q)
    const int ldr = tid >> 3;        // base row for loads (0..31), +32*i
    const int ldq = tid & 7;         // 16B chunk

    float d[2][8][4];
    #pragma unroll
    for (int mt = 0; mt < 2; mt++)
        #pragma unroll
        for (int nt = 0; nt < 8; nt++)
            #pragma unroll
            for (int v = 0; v < 4; v++) d[mt][nt][v] = 0.0f;

    // ---- prefetch stage 0 ----
    {
        const int k0 = 0;
        uint32_t sa = sb, sB = sb + 16384;
        #pragma unroll
        for (int i = 0; i < 4; i++) {
            int r = ldr + i * 32;
            uint32_t dsw = (uint32_t)(r * 128 + ((ldq ^ (r & 7)) << 4));
            CP_ASYNC16(sa + dsw, g_Ah + (m0 + r) * V + k0 + ldq * 8);
            CP_ASYNC16(sB + dsw, g_Bh + (gc0 + r) * V + k0 + ldq * 8);
        }
        CP_COMMIT();
    }

    #pragma unroll
    for (int t = 0; t < 4; t++) {
        // prefetch next stage
        if (t < 3) {
            const int k0 = (t + 1) * BK;
            uint32_t sa = sb + ((t + 1) & 1) * STAGE_BYTES;
            uint32_t sB = sa + 16384;
            #pragma unroll
            for (int i = 0; i < 4; i++) {
                int r = ldr + i * 32;
                uint32_t dsw = (uint32_t)(r * 128 + ((ldq ^ (r & 7)) << 4));
                CP_ASYNC16(sa + dsw, g_Ah + (m0 + r) * V + k0 + ldq * 8);
                CP_ASYNC16(sB + dsw, g_Bh + (gc0 + r) * V + k0 + ldq * 8);
            }
            CP_COMMIT();
            asm volatile("cp.async.wait_group 1;" ::: "memory");
        } else {
            asm volatile("cp.async.wait_group 0;" ::: "memory");
        }
        __syncthreads();

        const uint32_t sa = sb + (t & 1) * STAGE_BYTES;
        const uint32_t sB = sa + 16384;

        #pragma unroll
        for (int ks = 0; ks < 4; ks++) {
            // ---- A fragments: 2 m-tiles, ldmatrix.x4 each ----
            uint32_t a[2][4];
            #pragma unroll
            for (int mt = 0; mt < 2; mt++) {
                int r = wr * 32 + mt * 16 + (lane & 15);
                int q = ks * 2 + (lane >> 4);
                uint32_t addr = sa + r * 128 + ((q ^ (r & 7)) << 4);
                asm volatile("ldmatrix.sync.aligned.m8n8.x4.shared.b16 {%0,%1,%2,%3}, [%4];"
                    : "=r"(a[mt][0]), "=r"(a[mt][1]), "=r"(a[mt][2]), "=r"(a[mt][3])
                    : "r"(addr));
            }
            // ---- B fragments: 8 n-tiles via 4 ldmatrix.x4 ----
            uint32_t bf[8][2];
            #pragma unroll
            for (int p = 0; p < 4; p++) {
                int r = wc * 64 + p * 16 + (lane & 7) + ((lane >> 4) << 3);
                int q = ks * 2 + ((lane >> 3) & 1);
                uint32_t addr = sB + r * 128 + ((q ^ (r & 7)) << 4);
                uint32_t r0, r1, r2, r3;
                asm volatile("ldmatrix.sync.aligned.m8n8.x4.shared.b16 {%0,%1,%2,%3}, [%4];"
                    : "=r"(r0), "=r"(r1), "=r"(r2), "=r"(r3) : "r"(addr));
                bf[p * 2][0] = r0; bf[p * 2][1] = r1;
                bf[p * 2 + 1][0] = r2; bf[p * 2 + 1][1] = r3;
            }
            // ---- 16 MMAs ----
            #pragma unroll
            for (int mt = 0; mt < 2; mt++)
                #pragma unroll
                for (int nt = 0; nt < 8; nt++) {
                    asm volatile(
                        "mma.sync.aligned.m16n8k16.row.col.f32.f16.f16.f32 "
                        "{%0,%1,%2,%3}, {%4,%5,%6,%7}, {%8,%9}, {%0,%1,%2,%3};"
                        : "+f"(d[mt][nt][0]), "+f"(d[mt][nt][1]),
                          "+f"(d[mt][nt][2]), "+f"(d[mt][nt][3])
                        : "r"(a[mt][0]), "r"(a[mt][1]), "r"(a[mt][2]), "r"(a[mt][3]),
                          "r"(bf[nt][0]), "r"(bf[nt][1]));
                }
        }
        __syncthreads();
    }

    // ---- epilogue: tanh, gate, reduce over h=64 within the warp ----
    const int g   = lane >> 2;       // group id (row within 8)
    const int tig = lane & 3;
    const int Cg  = blockIdx.x * 2 + wc;                 // global channel
    const int gcb = gc0 + wc * 64;                       // global column base

    float p0[2] = {0.0f, 0.0f};      // row g (+mt*16), row g+8
    float p1[2] = {0.0f, 0.0f};
    #pragma unroll
    for (int nt = 0; nt < 8; nt++) {
        int gcol = gcb + nt * 8 + 2 * tig;
        float2 bi = *(const float2*)(b_in + gcol);
        float2 gt = *(const float2*)(g_gate + gcol);
        #pragma unroll
        for (int mt = 0; mt < 2; mt++) {
            float v0 = tanh_fast(d[mt][nt][0] + bi.x) * gt.x
                     + tanh_fast(d[mt][nt][1] + bi.y) * gt.y;
            float v1 = tanh_fast(d[mt][nt][2] + bi.x) * gt.x
                     + tanh_fast(d[mt][nt][3] + bi.y) * gt.y;
            p0[mt] += v0;
            p1[mt] += v1;
        }
    }
    // reduce across the 4-lane quad (tig)
    #pragma unroll
    for (int off = 1; off <= 2; off <<= 1) {
        #pragma unroll
        for (int mt = 0; mt < 2; mt++) {
            p0[mt] += __shfl_xor_sync(0xffffffffu, p0[mt], off);
            p1[mt] += __shfl_xor_sync(0xffffffffu, p1[mt], off);
        }
    }
    if (tig == 0) {
        float bo = __ldg(b_out + Cg);
        #pragma unroll
        for (int mt = 0; mt < 2; mt++) {
            int r0 = m0 + wr * 32 + mt * 16 + g;
            out[r0 * V + Cg]       = p0[mt] + bo;
            out[(r0 + 8) * V + Cg] = p1[mt] + bo;
        }
    }
}

// ---------------------------------------------------------------------------
extern "C" void kernel_launch(void* const* d_in, const int* in_sizes, int n_in,
                              void* d_out, int out_size) {
    const float* data    = (const float*)d_in[0];
    const float* adj     = (const float*)d_in[1];
    const float* neurons = (const float*)d_in[2];
    const float* w_in    = (const float*)d_in[3];
    const float* b_in    = (const float*)d_in[4];
    const float* w_out   = (const float*)d_in[5];
    const float* b_out   = (const float*)d_in[6];
    // d_in[7] = perm: analytic, never read.

    float* outp = (float*)d_out;
    int adj_off = out_size - N_SAMP * V;   // V*V = 65536
    float* out_main = outp + (adj_off > 0 ? adj_off : 0);

    prep_a_kernel<<<(N_SAMP * V + 255) / 256, 256>>>(data, adj, neurons, w_out, outp);
    dim3 gb(V, 4);
    prep_b_kernel<<<gb, 256>>>(adj, w_in);

    cudaFuncSetAttribute(fused_mma_kernel,
                         cudaFuncAttributeMaxDynamicSharedMemorySize, 2 * STAGE_BYTES);
    dim3 grid(NCOLS / 128, N_SAMP / 128);
    fused_mma_kernel<<<grid, 256, 2 * STAGE_BYTES>>>(b_in, b_out, out_main);
}